// round 1
// baseline (speedup 1.0000x reference)
#include <cuda_runtime.h>

#define BB 32
#define HH 56
#define HC 128
#define CC 256
#define PIX (HH*HH)          // 3136
#define EZ (BB*HC*PIX)       // 12845056
#define N1 (BB*PIX)          // 100352
#define OHH 112
#define OPIX (OHH*OHH)       // 12544
#define N2 (BB*OPIX)         // 401408

__device__ __align__(128) float g_z[EZ];      // conv1 out -> (in place) BEC output h
__device__ float g_m1[HC], g_rs1[HC];
__device__ float g_m2[CC], g_rs2[CC];

// ---------------------------------------------------------------------------
// Kernel 1: conv 3x3, stride 1, pad 1, in-ch 257 (ch 256 = constant noise
// plane), out-ch 128.  Tile: 8x8 pixels x 128 oc per block, 256 threads.
// ---------------------------------------------------------------------------
__global__ __launch_bounds__(256) void conv1_kernel(
    const float* __restrict__ x, const float* __restrict__ nu,
    const float* __restrict__ w1, const float* __restrict__ b1) {
  __shared__ float sIn[10 * 12];
  __shared__ float sW[9 * 128];
  const int t = threadIdx.x;
  const int bx = blockIdx.x, by = blockIdx.y, b = blockIdx.z;
  const float nf = nu[0] * 0.5f;

  const int p0  = 2 * (t & 31);          // pixel pair (same row)
  const int py  = p0 >> 3, px0 = p0 & 7;
  const int ocb = (t >> 5) * 16;         // 16 output channels per thread

  float acc[32];
#pragma unroll
  for (int i = 0; i < 32; ++i) acc[i] = 0.f;

  const int gy0 = by * 8 - 1, gx0 = bx * 8 - 1;

  for (int ic = 0; ic < 257; ++ic) {
    __syncthreads();
    if (t < 100) {
      int r = t / 10, cix = t % 10;
      int gy = gy0 + r, gx = gx0 + cix;
      float v = 0.f;
      if (gy >= 0 && gy < HH && gx >= 0 && gx < HH)
        v = (ic < 256) ? x[((b * 256 + ic) * HH + gy) * HH + gx] : nf;
      sIn[r * 12 + cix] = v;
    }
    for (int i = t; i < 1152; i += 256) {
      int oc = i / 9, kk = i % 9;
      sW[kk * 128 + oc] = w1[oc * 2313 + ic * 9 + kk];
    }
    __syncthreads();
#pragma unroll
    for (int kk = 0; kk < 9; ++kk) {
      const int kh = kk / 3, kw = kk % 3;
      const float i0 = sIn[(py + kh) * 12 + px0 + kw];
      const float i1 = sIn[(py + kh) * 12 + px0 + 1 + kw];
      const float4* wv = (const float4*)&sW[kk * 128 + ocb];
#pragma unroll
      for (int j4 = 0; j4 < 4; ++j4) {
        float4 w = wv[j4];
        acc[(j4 * 4 + 0) * 2 + 0] += w.x * i0; acc[(j4 * 4 + 0) * 2 + 1] += w.x * i1;
        acc[(j4 * 4 + 1) * 2 + 0] += w.y * i0; acc[(j4 * 4 + 1) * 2 + 1] += w.y * i1;
        acc[(j4 * 4 + 2) * 2 + 0] += w.z * i0; acc[(j4 * 4 + 2) * 2 + 1] += w.z * i1;
        acc[(j4 * 4 + 3) * 2 + 0] += w.w * i0; acc[(j4 * 4 + 3) * 2 + 1] += w.w * i1;
      }
    }
  }
  const int oy = by * 8 + py, ox = bx * 8 + px0;
#pragma unroll
  for (int j = 0; j < 16; ++j) {
    const int oc = ocb + j;
    const float bb = b1[oc];
    const int base = ((b * 128 + oc) * HH + oy) * HH + ox;
    g_z[base]     = acc[2 * j]     + bb;
    g_z[base + 1] = acc[2 * j + 1] + bb;
  }
}

// ---------------------------------------------------------------------------
// Kernel 2: BN1 stats (double accumulation, one block per channel)
// ---------------------------------------------------------------------------
__global__ __launch_bounds__(256) void stats1_kernel() {
  const int c = blockIdx.x, t = threadIdx.x;
  double s = 0.0, q = 0.0;
  for (int i = t; i < N1; i += 256) {
    int b = i / PIX, p = i % PIX;
    float v = g_z[(b * 128 + c) * PIX + p];
    s += v; q += (double)v * v;
  }
  __shared__ double ss[256], sq[256];
  ss[t] = s; sq[t] = q;
  __syncthreads();
  for (int o = 128; o > 0; o >>= 1) {
    if (t < o) { ss[t] += ss[t + o]; sq[t] += sq[t + o]; }
    __syncthreads();
  }
  if (t == 0) {
    double m   = ss[0] / N1;
    double var = sq[0] / N1 - m * m;
    g_m1[c]  = (float)m;
    g_rs1[c] = rsqrtf((float)var + 1e-5f);
  }
}

// ---------------------------------------------------------------------------
// Threefry2x32, key = jax.random.key(42) = (0, 42).
// Partitionable mode 32-bit draw for flat index j (< 2^32): x0=0, x1=j,
// output = out0 ^ out1.
// ---------------------------------------------------------------------------
__device__ __forceinline__ unsigned tf_xor(unsigned j) {
  const unsigned ks0 = 0u, ks1 = 42u, ks2 = 0x1BD11BDAu ^ 42u;
  unsigned x0 = 0u + ks0;
  unsigned x1 = j  + ks1;
#define TFRND(r) { x0 += x1; x1 = __funnelshift_l(x1, x1, r); x1 ^= x0; }
  TFRND(13) TFRND(15) TFRND(26) TFRND(6)
  x0 += ks1; x1 += ks2 + 1u;
  TFRND(17) TFRND(29) TFRND(16) TFRND(24)
  x0 += ks2; x1 += ks0 + 2u;
  TFRND(13) TFRND(15) TFRND(26) TFRND(6)
  x0 += ks0; x1 += ks1 + 3u;
  TFRND(17) TFRND(29) TFRND(16) TFRND(24)
  x0 += ks1; x1 += ks2 + 4u;
  TFRND(13) TFRND(15) TFRND(26) TFRND(6)
  x0 += ks2; x1 += ks0 + 5u;
#undef TFRND
  return x0 ^ x1;
}

// ---------------------------------------------------------------------------
// Kernel 3: BN1 apply + sigmoid + byte-quantize + binary erasure channel,
// in place on g_z.
// ---------------------------------------------------------------------------
__global__ __launch_bounds__(256) void bec_kernel(
    const float* __restrict__ nu, const float* __restrict__ g1,
    const float* __restrict__ be1) {
  const int e = blockIdx.x * 256 + threadIdx.x;
  const int c = (e / PIX) & 127;
  const float z = g_z[e];
  // BN (ref order) then XLA LogisticExpander form of sigmoid
  float tt = (z - g_m1[c]) * g_rs1[c] * g1[c] + be1[c];
  float s  = 0.5f * tanhf(0.5f * tt) + 0.5f;
  float r  = rintf(s * 256.0f);
  if (r >= 256.0f) r -= 256.0f;       // round(x*256) % 256
  const unsigned xb = (unsigned)r;

  const float q = 1.0f - nu[0] * 0.5f;   // bernoulli prob (1 - p)
  unsigned mask = 0u;
#pragma unroll
  for (int k = 0; k < 8; ++k) {
    unsigned bits = tf_xor((unsigned)(k * EZ + e));
    float u = __uint_as_float((bits >> 9) | 0x3f800000u) - 1.0f;
    if (u < q) mask |= (1u << k);
  }
  float outv = ((float)(xb & mask) + (255.0f - (float)mask) / 2.0f) / 255.0f;
  g_z[e] = outv;
}

// ---------------------------------------------------------------------------
// Kernel 4: ConvTranspose2d(k2,s2) == per-input-pixel 4-tap GEMM:
//   y[b,c,2ih+kh,2iw+kw] = b4[c] + sum_hc h[b,hc,ih,iw] * w4[hc,c,kh,kw]
// Tile: 32 input px x 64 out-ch x 4 taps per block.
// ---------------------------------------------------------------------------
__global__ __launch_bounds__(256) void dec_kernel(
    const float* __restrict__ w4, const float* __restrict__ b4,
    float* __restrict__ out) {
  __shared__ float4 ws4[16 * 64];   // [hc-chunk][c-local] -> 4 taps
  __shared__ float4 hs4[16 * 8];    // [hc-chunk][px/4]
  const int t = threadIdx.x;
  const int g0   = blockIdx.x * 32;
  const int b    = g0 / PIX;
  const int pixb = g0 % PIX;
  const int cb   = blockIdx.y * 64;
  const int lpx  = t & 7;           // which group of 4 pixels
  const int cl2  = (t >> 3) * 2;    // 2 local channels

  float acc[32];
#pragma unroll
  for (int i = 0; i < 32; ++i) acc[i] = 0.f;

  for (int hc0 = 0; hc0 < 128; hc0 += 16) {
    __syncthreads();
    for (int i = t; i < 1024; i += 256) {
      int hh = i >> 6, cl = i & 63;
      ws4[i] = *(const float4*)(w4 + (hc0 + hh) * 1024 + (cb + cl) * 4);
    }
    if (t < 128) {
      int hh = t >> 3, p4 = t & 7;
      hs4[t] = *(const float4*)(g_z + (b * 128 + hc0 + hh) * PIX + pixb + p4 * 4);
    }
    __syncthreads();
#pragma unroll
    for (int hh = 0; hh < 16; ++hh) {
      const float4 h4 = hs4[hh * 8 + lpx];
      const float4 wa = ws4[hh * 64 + cl2];
      const float4 wb = ws4[hh * 64 + cl2 + 1];
      const float hv[4] = {h4.x, h4.y, h4.z, h4.w};
#pragma unroll
      for (int p = 0; p < 4; ++p) {
        acc[p * 4 + 0]      += hv[p] * wa.x;
        acc[p * 4 + 1]      += hv[p] * wa.y;
        acc[p * 4 + 2]      += hv[p] * wa.z;
        acc[p * 4 + 3]      += hv[p] * wa.w;
        acc[16 + p * 4 + 0] += hv[p] * wb.x;
        acc[16 + p * 4 + 1] += hv[p] * wb.y;
        acc[16 + p * 4 + 2] += hv[p] * wb.z;
        acc[16 + p * 4 + 3] += hv[p] * wb.w;
      }
    }
  }
#pragma unroll
  for (int cc = 0; cc < 2; ++cc) {
    const int c = cb + cl2 + cc;
    const float bbv = b4[c];
#pragma unroll
    for (int p = 0; p < 4; ++p) {
      const int pix = pixb + lpx * 4 + p;
      const int ih = pix / HH, iw = pix % HH;
      const int base = ((b * 256 + c) * OHH + 2 * ih) * OHH + 2 * iw;
      out[base]           = acc[cc * 16 + p * 4 + 0] + bbv;  // kh0 kw0
      out[base + 1]       = acc[cc * 16 + p * 4 + 1] + bbv;  // kh0 kw1
      out[base + OHH]     = acc[cc * 16 + p * 4 + 2] + bbv;  // kh1 kw0
      out[base + OHH + 1] = acc[cc * 16 + p * 4 + 3] + bbv;  // kh1 kw1
    }
  }
}

// ---------------------------------------------------------------------------
// Kernel 5: BN2 stats (double accumulation)
// ---------------------------------------------------------------------------
__global__ __launch_bounds__(256) void stats2_kernel(const float* __restrict__ out) {
  const int c = blockIdx.x, t = threadIdx.x;
  double s = 0.0, q = 0.0;
  for (int i = t; i < N2 / 4; i += 256) {
    int b = i / (OPIX / 4), p4 = i % (OPIX / 4);
    float4 v = *(const float4*)(out + (b * 256 + c) * OPIX + p4 * 4);
    s += (double)v.x + v.y + v.z + v.w;
    q += (double)v.x * v.x + (double)v.y * v.y +
         (double)v.z * v.z + (double)v.w * v.w;
  }
  __shared__ double ss[256], sq[256];
  ss[t] = s; sq[t] = q;
  __syncthreads();
  for (int o = 128; o > 0; o >>= 1) {
    if (t < o) { ss[t] += ss[t + o]; sq[t] += sq[t + o]; }
    __syncthreads();
  }
  if (t == 0) {
    double m   = ss[0] / N2;
    double var = sq[0] / N2 - m * m;
    g_m2[c]  = (float)m;
    g_rs2[c] = rsqrtf((float)var + 1e-5f);
  }
}

// ---------------------------------------------------------------------------
// Kernel 6: BN2 apply + relu, in place on d_out (vectorized float4)
// ---------------------------------------------------------------------------
__global__ __launch_bounds__(256) void bn2_kernel(
    const float* __restrict__ g2, const float* __restrict__ be2,
    float* __restrict__ out) {
  const int i = blockIdx.x * 256 + threadIdx.x;     // float4 index
  const int c = (i / (OPIX / 4)) & 255;
  float4 v = ((float4*)out)[i];
  const float m = g_m2[c], rs = g_rs2[c], gg = g2[c], bb = be2[c];
  v.x = fmaxf((v.x - m) * rs * gg + bb, 0.f);
  v.y = fmaxf((v.y - m) * rs * gg + bb, 0.f);
  v.z = fmaxf((v.z - m) * rs * gg + bb, 0.f);
  v.w = fmaxf((v.w - m) * rs * gg + bb, 0.f);
  ((float4*)out)[i] = v;
}

// ---------------------------------------------------------------------------
extern "C" void kernel_launch(void* const* d_in, const int* in_sizes, int n_in,
                              void* d_out, int out_size) {
  const float* x   = (const float*)d_in[0];
  const float* nu  = (const float*)d_in[1];
  const float* w1  = (const float*)d_in[2];
  const float* b1  = (const float*)d_in[3];
  const float* g1  = (const float*)d_in[4];
  const float* be1 = (const float*)d_in[5];
  const float* w4  = (const float*)d_in[6];
  const float* b4  = (const float*)d_in[7];
  const float* g2  = (const float*)d_in[8];
  const float* be2 = (const float*)d_in[9];
  float* out = (float*)d_out;

  conv1_kernel<<<dim3(7, 7, 32), 256>>>(x, nu, w1, b1);
  stats1_kernel<<<128, 256>>>();
  bec_kernel<<<EZ / 256, 256>>>(nu, g1, be1);
  dec_kernel<<<dim3((BB * PIX) / 32, 4), 256>>>(w4, b4, out);
  stats2_kernel<<<256, 256>>>(out);
  bn2_kernel<<<out_size / 4 / 256, 256>>>(g2, be2, out);
}

// round 2
// speedup vs baseline: 1.4792x; 1.4792x over previous
#include <cuda_runtime.h>

#define BB 32
#define HH 56
#define HC 128
#define CC 256
#define PIX (HH*HH)          // 3136
#define EZ (BB*HC*PIX)       // 12845056
#define N1 (BB*PIX)          // 100352
#define OHH 112
#define OPIX (OHH*OHH)       // 12544
#define N2 (BB*OPIX)         // 401408
#define KW1 (257*9)          // 2313

__device__ __align__(128) float g_z[EZ];        // conv1 out -> (in place) BEC output h
__device__ __align__(128) float g_wp[KW1*128];  // repacked w1: [ic*9+kk][oc]
__device__ float g_m1[HC], g_rs1[HC];
__device__ float g_m2[CC], g_rs2[CC];

// ---------------------------------------------------------------------------
// Kernel 0: repack w1 [oc][ic][kk] -> g_wp [ic*9+kk][oc]
// ---------------------------------------------------------------------------
__global__ __launch_bounds__(256) void repack_kernel(const float* __restrict__ w1) {
  int i = blockIdx.x * 256 + threadIdx.x;   // over 2313*128
  if (i < KW1 * 128) {
    int oc = i & 127, ickk = i >> 7;
    g_wp[ickk * 128 + oc] = w1[oc * KW1 + ickk];
  }
}

// ---------------------------------------------------------------------------
// Kernel 1: conv 3x3 s1 p1, 257 in-ch (ch256 = noise const), 128 out-ch.
// Tile: 128 oc x (8 rows x 16 cols) px.  256 threads, 8oc x 8px microtile.
// Register prefetch of next ic overlapped with compute.
// ---------------------------------------------------------------------------
__global__ __launch_bounds__(256) void conv1_kernel(
    const float* __restrict__ x, const float* __restrict__ nu,
    const float* __restrict__ b1) {
  __shared__ float sIn[180];      // 10 rows x 18 cols halo
  __shared__ float4 sW[288];      // 9 kk x 128 oc (as float4)
  const int t = threadIdx.x;
  const int bx = blockIdx.x, by = blockIdx.y, b = blockIdx.z;
  const float nf = nu[0] * 0.5f;

  const int og = t >> 4;             // oc group: oc base = og*8
  const int p  = t & 15;
  const int row = p >> 1;            // 0..7 within tile
  const int cbase = (p & 1) * 8;     // 0 or 8
  const int r0 = by * 8, c0 = bx * 16;

  // input loader coords (threads 0..179)
  const int lr = t / 18, lc = t % 18;
  const int gy = r0 - 1 + lr, gx = c0 - 1 + lc;
  const bool inb = (t < 180) && (gy >= 0) && (gy < HH) && (gx >= 0) && (gx < HH);
  const long xoff = ((long)b * 256) * PIX + (long)gy * HH + gx;

  float acc[64];
#pragma unroll
  for (int i = 0; i < 64; ++i) acc[i] = 0.f;

  const float4* wp4 = (const float4*)g_wp;

  // prologue: stage ic=0
  {
    float v = 0.f;
    if (inb) v = x[xoff];            // ic=0
    float4 wa = wp4[t];
    float4 wb;
    if (t < 32) wb = wp4[256 + t];
    if (t < 180) sIn[t] = v;
    sW[t] = wa;
    if (t < 32) sW[256 + t] = wb;
  }
  __syncthreads();

  float pin = 0.f;
  float4 pwa, pwb;

  for (int ic = 0; ic < 257; ++ic) {
    // prefetch ic+1 into registers (overlaps with compute below)
    if (ic < 256) {
      const int icn = ic + 1;
      pin = 0.f;
      if (inb) pin = (icn < 256) ? x[xoff + (long)icn * PIX] : nf;
      pwa = wp4[icn * 288 + t];
      if (t < 32) pwb = wp4[icn * 288 + 256 + t];
    }

    // compute current ic from smem
#pragma unroll
    for (int kh = 0; kh < 3; ++kh) {
      float inr[10];
#pragma unroll
      for (int j = 0; j < 10; ++j) inr[j] = sIn[(row + kh) * 18 + cbase + j];
#pragma unroll
      for (int kw = 0; kw < 3; ++kw) {
        const int kk = kh * 3 + kw;
        const float4 wa = sW[kk * 32 + og * 2];
        const float4 wb = sW[kk * 32 + og * 2 + 1];
#pragma unroll
        for (int j = 0; j < 8; ++j) {
          const float iv = inr[kw + j];
          acc[0 * 8 + j] += wa.x * iv;
          acc[1 * 8 + j] += wa.y * iv;
          acc[2 * 8 + j] += wa.z * iv;
          acc[3 * 8 + j] += wa.w * iv;
          acc[4 * 8 + j] += wb.x * iv;
          acc[5 * 8 + j] += wb.y * iv;
          acc[6 * 8 + j] += wb.z * iv;
          acc[7 * 8 + j] += wb.w * iv;
        }
      }
    }

    __syncthreads();
    if (ic < 256) {
      if (t < 180) sIn[t] = pin;
      sW[t] = pwa;
      if (t < 32) sW[256 + t] = pwb;
    }
    __syncthreads();
  }

  // epilogue: +bias, store (predicate right-edge tiles)
  if (c0 + cbase < HH) {
#pragma unroll
    for (int ocl = 0; ocl < 8; ++ocl) {
      const int oc = og * 8 + ocl;
      const float bb = b1[oc];
      float* dst = g_z + ((b * 128 + oc) * HH + r0 + row) * HH + c0 + cbase;
      float4 v0 = {acc[ocl*8+0]+bb, acc[ocl*8+1]+bb, acc[ocl*8+2]+bb, acc[ocl*8+3]+bb};
      float4 v1 = {acc[ocl*8+4]+bb, acc[ocl*8+5]+bb, acc[ocl*8+6]+bb, acc[ocl*8+7]+bb};
      ((float4*)dst)[0] = v0;
      ((float4*)dst)[1] = v1;
    }
  }
}

// ---------------------------------------------------------------------------
// Kernel 2: BN1 stats (double accumulation, one block per channel)
// ---------------------------------------------------------------------------
__global__ __launch_bounds__(256) void stats1_kernel() {
  const int c = blockIdx.x, t = threadIdx.x;
  double s = 0.0, q = 0.0;
  for (int i = t; i < N1; i += 256) {
    int b = i / PIX, p = i % PIX;
    float v = g_z[(b * 128 + c) * PIX + p];
    s += v; q += (double)v * v;
  }
  __shared__ double ss[256], sq[256];
  ss[t] = s; sq[t] = q;
  __syncthreads();
  for (int o = 128; o > 0; o >>= 1) {
    if (t < o) { ss[t] += ss[t + o]; sq[t] += sq[t + o]; }
    __syncthreads();
  }
  if (t == 0) {
    double m   = ss[0] / N1;
    double var = sq[0] / N1 - m * m;
    g_m1[c]  = (float)m;
    g_rs1[c] = rsqrtf((float)var + 1e-5f);
  }
}

// ---------------------------------------------------------------------------
// Threefry2x32, key (0,42), partitionable-mode draw for index j: x0=0, x1=j,
// 32-bit output = out0 ^ out1.
// ---------------------------------------------------------------------------
__device__ __forceinline__ unsigned tf_xor(unsigned j) {
  const unsigned ks0 = 0u, ks1 = 42u, ks2 = 0x1BD11BDAu ^ 42u;
  unsigned x0 = 0u + ks0;
  unsigned x1 = j  + ks1;
#define TFRND(r) { x0 += x1; x1 = __funnelshift_l(x1, x1, r); x1 ^= x0; }
  TFRND(13) TFRND(15) TFRND(26) TFRND(6)
  x0 += ks1; x1 += ks2 + 1u;
  TFRND(17) TFRND(29) TFRND(16) TFRND(24)
  x0 += ks2; x1 += ks0 + 2u;
  TFRND(13) TFRND(15) TFRND(26) TFRND(6)
  x0 += ks0; x1 += ks1 + 3u;
  TFRND(17) TFRND(29) TFRND(16) TFRND(24)
  x0 += ks1; x1 += ks2 + 4u;
  TFRND(13) TFRND(15) TFRND(26) TFRND(6)
  x0 += ks2; x1 += ks0 + 5u;
#undef TFRND
  return x0 ^ x1;
}

// ---------------------------------------------------------------------------
// Kernel 3: BN1 apply + sigmoid + byte-quantize + BEC, in place on g_z.
// ---------------------------------------------------------------------------
__global__ __launch_bounds__(256) void bec_kernel(
    const float* __restrict__ nu, const float* __restrict__ g1,
    const float* __restrict__ be1) {
  const int e = blockIdx.x * 256 + threadIdx.x;
  const int c = (e / PIX) & 127;
  const float z = g_z[e];
  float tt = (z - g_m1[c]) * g_rs1[c] * g1[c] + be1[c];
  float s  = 0.5f * tanhf(0.5f * tt) + 0.5f;
  float r  = rintf(s * 256.0f);
  if (r >= 256.0f) r -= 256.0f;
  const unsigned xb = (unsigned)r;

  const float q = 1.0f - nu[0] * 0.5f;
  unsigned mask = 0u;
#pragma unroll
  for (int k = 0; k < 8; ++k) {
    unsigned bits = tf_xor((unsigned)(k * EZ + e));
    float u = __uint_as_float((bits >> 9) | 0x3f800000u) - 1.0f;
    if (u < q) mask |= (1u << k);
  }
  float outv = ((float)(xb & mask) + (255.0f - (float)mask) / 2.0f) / 255.0f;
  g_z[e] = outv;
}

// ---------------------------------------------------------------------------
// Kernel 4: ConvTranspose2d(k2,s2) as 4-tap GEMM.
// Tile: 64 px x 64 oc x 4 taps; 256 threads, 8px x 2c x 4tap = 64 acc each.
// ---------------------------------------------------------------------------
__global__ __launch_bounds__(256) void dec_kernel(
    const float* __restrict__ w4, const float* __restrict__ b4,
    float* __restrict__ out) {
  __shared__ float4 ws4[16 * 64];   // [hc-chunk][c-local] -> 4 taps
  __shared__ float4 hs4[16 * 16];   // [hc-chunk][px/4]
  const int t = threadIdx.x;
  const int bp = blockIdx.x;
  const int b = bp / 49;
  const int pixb = (bp % 49) * 64;
  const int cb = blockIdx.y * 64;
  const int pgrp = t & 7;           // 8 px groups of 8
  const int cgrp = t >> 3;          // 0..31, 2 channels each

  float acc[64];                    // [cc2][px8][tap4] = cc*32 + p*4 + tap
#pragma unroll
  for (int i = 0; i < 64; ++i) acc[i] = 0.f;

  const float4* w44 = (const float4*)w4;
  const float4* gz4 = (const float4*)g_z;

  for (int hc0 = 0; hc0 < 128; hc0 += 16) {
    __syncthreads();
#pragma unroll
    for (int i = 0; i < 4; ++i) {
      int idx = t + i * 256;
      int hh = idx >> 6, cl = idx & 63;
      ws4[idx] = w44[(hc0 + hh) * 256 + cb + cl];
    }
    {
      int hh = t >> 4, p4 = t & 15;
      hs4[t] = gz4[((b * 128 + hc0 + hh) * PIX + pixb) / 4 + p4];
    }
    __syncthreads();
#pragma unroll
    for (int hh = 0; hh < 16; ++hh) {
      const float4 h0 = hs4[hh * 16 + pgrp * 2];
      const float4 h1 = hs4[hh * 16 + pgrp * 2 + 1];
      const float4 wa = ws4[hh * 64 + cgrp * 2];
      const float4 wb = ws4[hh * 64 + cgrp * 2 + 1];
      const float hv[8] = {h0.x, h0.y, h0.z, h0.w, h1.x, h1.y, h1.z, h1.w};
#pragma unroll
      for (int pp = 0; pp < 8; ++pp) {
        acc[pp * 4 + 0] += hv[pp] * wa.x;
        acc[pp * 4 + 1] += hv[pp] * wa.y;
        acc[pp * 4 + 2] += hv[pp] * wa.z;
        acc[pp * 4 + 3] += hv[pp] * wa.w;
        acc[32 + pp * 4 + 0] += hv[pp] * wb.x;
        acc[32 + pp * 4 + 1] += hv[pp] * wb.y;
        acc[32 + pp * 4 + 2] += hv[pp] * wb.z;
        acc[32 + pp * 4 + 3] += hv[pp] * wb.w;
      }
    }
  }

#pragma unroll
  for (int cc = 0; cc < 2; ++cc) {
    const int c = cb + cgrp * 2 + cc;
    const float bb = b4[c];
#pragma unroll
    for (int pp = 0; pp < 8; ++pp) {
      const int pix = pixb + pgrp * 8 + pp;
      const int ih = pix / HH, iw = pix % HH;
      float* dst = out + ((b * 256 + c) * OHH + 2 * ih) * OHH + 2 * iw;
      float2 top = {acc[cc * 32 + pp * 4 + 0] + bb, acc[cc * 32 + pp * 4 + 1] + bb};
      float2 bot = {acc[cc * 32 + pp * 4 + 2] + bb, acc[cc * 32 + pp * 4 + 3] + bb};
      *(float2*)dst = top;
      *(float2*)(dst + OHH) = bot;
    }
  }
}

// ---------------------------------------------------------------------------
// Kernel 5: BN2 stats (double accumulation)
// ---------------------------------------------------------------------------
__global__ __launch_bounds__(256) void stats2_kernel(const float* __restrict__ out) {
  const int c = blockIdx.x, t = threadIdx.x;
  double s = 0.0, q = 0.0;
  for (int i = t; i < N2 / 4; i += 256) {
    int b = i / (OPIX / 4), p4 = i % (OPIX / 4);
    float4 v = *(const float4*)(out + (b * 256 + c) * OPIX + p4 * 4);
    s += (double)v.x + v.y + v.z + v.w;
    q += (double)v.x * v.x + (double)v.y * v.y +
         (double)v.z * v.z + (double)v.w * v.w;
  }
  __shared__ double ss[256], sq[256];
  ss[t] = s; sq[t] = q;
  __syncthreads();
  for (int o = 128; o > 0; o >>= 1) {
    if (t < o) { ss[t] += ss[t + o]; sq[t] += sq[t + o]; }
    __syncthreads();
  }
  if (t == 0) {
    double m   = ss[0] / N2;
    double var = sq[0] / N2 - m * m;
    g_m2[c]  = (float)m;
    g_rs2[c] = rsqrtf((float)var + 1e-5f);
  }
}

// ---------------------------------------------------------------------------
// Kernel 6: BN2 apply + relu, in place on d_out
// ---------------------------------------------------------------------------
__global__ __launch_bounds__(256) void bn2_kernel(
    const float* __restrict__ g2, const float* __restrict__ be2,
    float* __restrict__ out) {
  const int i = blockIdx.x * 256 + threadIdx.x;     // float4 index
  const int c = (i / (OPIX / 4)) & 255;
  float4 v = ((float4*)out)[i];
  const float m = g_m2[c], rs = g_rs2[c], gg = g2[c], bb = be2[c];
  v.x = fmaxf((v.x - m) * rs * gg + bb, 0.f);
  v.y = fmaxf((v.y - m) * rs * gg + bb, 0.f);
  v.z = fmaxf((v.z - m) * rs * gg + bb, 0.f);
  v.w = fmaxf((v.w - m) * rs * gg + bb, 0.f);
  ((float4*)out)[i] = v;
}

// ---------------------------------------------------------------------------
extern "C" void kernel_launch(void* const* d_in, const int* in_sizes, int n_in,
                              void* d_out, int out_size) {
  const float* x   = (const float*)d_in[0];
  const float* nu  = (const float*)d_in[1];
  const float* w1  = (const float*)d_in[2];
  const float* b1  = (const float*)d_in[3];
  const float* g1  = (const float*)d_in[4];
  const float* be1 = (const float*)d_in[5];
  const float* w4  = (const float*)d_in[6];
  const float* b4  = (const float*)d_in[7];
  const float* g2  = (const float*)d_in[8];
  const float* be2 = (const float*)d_in[9];
  float* out = (float*)d_out;

  repack_kernel<<<(KW1 * 128 + 255) / 256, 256>>>(w1);
  conv1_kernel<<<dim3(4, 7, 32), 256>>>(x, nu, b1);
  stats1_kernel<<<128, 256>>>();
  bec_kernel<<<EZ / 256, 256>>>(nu, g1, be1);
  dec_kernel<<<dim3(32 * 49, 4), 256>>>(w4, b4, out);
  stats2_kernel<<<256, 256>>>(out);
  bn2_kernel<<<out_size / 4 / 256, 256>>>(g2, be2, out);
}